// round 7
// baseline (speedup 1.0000x reference)
#include <cuda_runtime.h>
#include <math.h>
#include <stdint.h>

#define BB  256
#define NN  1024
#define C1  101
#define DD  256
#define HH  16
#define NEGV (-1000000000.0f)
#define AS  104          // att row stride (floats)
#define WS  260          // w_sh row stride (floats); 16*WS = 4160
#define WROW (HH * WS)

__device__ __align__(16) float g_u[BB * HH * DD];     // u[b][h][d]
__device__ __align__(16) float g_w[BB * HH * DD];     // weighted ce per head
__device__ __align__(16) float g_part[2 * BB * 4 * DD];
__device__ int g_cnt[2 * BB * 4];

__device__ __forceinline__ bool readb(const void* p, int idx, int mode) {
    if (mode == 0) return ((const unsigned char*)p)[idx] != 0;
    if (mode == 1) return ((const int*)p)[idx] != 0;
    return ((const float*)p)[idx] != 0.0f;
}

__device__ __forceinline__ float dot4(float4 a, float4 b) {
    return a.x * b.x + a.y * b.y + a.z * b.z + a.w * b.w;
}

__device__ __forceinline__ unsigned long long pack2(float x) {
    unsigned long long r;
    asm("mov.b64 %0, {%1, %1};" : "=l"(r) : "f"(x));
    return r;
}
__device__ __forceinline__ void fma2(unsigned long long& acc, unsigned long long a,
                                     unsigned long long b) {
    asm("fma.rn.f32x2 %0, %1, %2, %0;" : "+l"(acc) : "l"(a), "l"(b));
}
union U64F2 { unsigned long long u; float2 f; };

// bool-dtype probe on first 4KB of `mask`. Call from ALL threads (sync-or).
__device__ __forceinline__ int detect_mode(const void* m, int t) {
    int f32 = 0, u8 = 0;
    if (t < 256) {
        uint4 v = ((const uint4*)m)[t];
        unsigned w[4] = {v.x, v.y, v.z, v.w};
#pragma unroll
        for (int i = 0; i < 4; i++) {
            unsigned x = w[i];
            if (((x >> 24) & 0xffu) == 0x3fu || ((x >> 16) & 0xffu) == 0x3fu ||
                ((x >> 8) & 0xffu) == 0x3fu || (x & 0xffu) == 0x3fu) f32 = 1;
            if (x & 0xffffff00u) u8 = 1;
        }
    }
    int a = __syncthreads_or(f32);
    int b = __syncthreads_or(u8);
    return a ? 2 : (b ? 0 : 1);
}

// ---------------- Kernel 1: node partial sums (1024 CTAs) --------------------
__global__ void __launch_bounds__(256) k_nodes_part(
    const float* __restrict__ node, const void* __restrict__ mask,
    const void* __restrict__ cmask)
{
    __shared__ unsigned char code[256];
    __shared__ float4 part[2][4][64];

    int q = blockIdx.x, b = blockIdx.y, t = threadIdx.x;
    int mode = detect_mode(mask, t);

    int gidx = b * NN + q * 256 + t;
    bool m  = readb(mask,  gidx, mode);
    bool mc = m | readb(cmask, gidx, mode);
    code[t] = (unsigned char)((m ? 1 : 0) | (mc ? 2 : 0));
    int c0 = __syncthreads_count(!m);
    int c1 = __syncthreads_count(!mc);

    int chunk = t >> 6, d4 = t & 63;
    const float4* np4 = (const float4*)(node + (size_t)b * NN * DD);
    float4 s0 = make_float4(0.f, 0.f, 0.f, 0.f), s1 = s0;
    int n0 = chunk * 64;
#pragma unroll 8
    for (int i = 0; i < 64; i++) {
        int n = n0 + i;
        float4 v = __ldcs(&np4[(size_t)(q * 256 + n) * 64 + d4]);
        unsigned char c = code[n];
        if (!(c & 1)) { s0.x += v.x; s0.y += v.y; s0.z += v.z; s0.w += v.w; }
        if (!(c & 2)) { s1.x += v.x; s1.y += v.y; s1.z += v.z; s1.w += v.w; }
    }
    part[0][chunk][d4] = s0;
    part[1][chunk][d4] = s1;
    __syncthreads();

    if (t < 128) {
        int which = t >> 6, d = t & 63;
        float4 r = make_float4(0.f, 0.f, 0.f, 0.f);
#pragma unroll
        for (int c = 0; c < 4; c++) {
            float4 a = part[which][c][d];
            r.x += a.x; r.y += a.y; r.z += a.z; r.w += a.w;
        }
        ((float4*)g_part)[((which * BB + b) * 4 + q) * 64 + d] = r;
    }
    if (t == 0) {
        g_cnt[(0 * BB + b) * 4 + q] = c0;
        g_cnt[(1 * BB + b) * 4 + q] = c1;
    }
}

// ---------------- Kernel 2: q + u (uv reduced inline from partials) ----------
__global__ void __launch_bounds__(256) k_qu(
    const float* __restrict__ cur, const float* __restrict__ depot,
    const float* __restrict__ Wq, const float* __restrict__ Wk)
{
    __shared__ __align__(16) float ctx_s[8][768];
    __shared__ __align__(16) float qp[8][8][32];
    __shared__ __align__(16) float q_s[8][32];
    __shared__ float den_s[8];

    int cx = blockIdx.x;     // 0..7 : 32-col slice = 2 heads
    int by = blockIdx.y;     // 0..31: 8 batches
    int t = threadIdx.x, lane = t & 31, w = t >> 5;

    if (t < 8) {
        int b = by * 8 + t;
        int c = g_cnt[b * 4 + 0] + g_cnt[b * 4 + 1] + g_cnt[b * 4 + 2] + g_cnt[b * 4 + 3];
        den_s[t] = fmaxf((float)c, 1.0f);
    }
    __syncthreads();

    for (int i = t; i < 8 * 256; i += 256) {
        int bi = i >> 8, d = i & 255;
        int b = by * 8 + bi;
        float s = g_part[(size_t)(b * 4 + 0) * 256 + d] + g_part[(size_t)(b * 4 + 1) * 256 + d]
                + g_part[(size_t)(b * 4 + 2) * 256 + d] + g_part[(size_t)(b * 4 + 3) * 256 + d];
        ctx_s[bi][d]       = s / den_s[bi];
        ctx_s[bi][256 + d] = cur[(size_t)b * DD + d];
        ctx_s[bi][512 + d] = depot[(size_t)b * DD + d];
    }
    __syncthreads();

    {
        int c = cx * 32 + lane;
        float acc[8];
#pragma unroll
        for (int bi = 0; bi < 8; bi++) acc[bi] = 0.f;
        int k0 = w * 96;
        for (int k = k0; k < k0 + 96; k += 4) {
            float w0 = Wq[(size_t)(k + 0) * 256 + c];
            float w1 = Wq[(size_t)(k + 1) * 256 + c];
            float w2 = Wq[(size_t)(k + 2) * 256 + c];
            float w3 = Wq[(size_t)(k + 3) * 256 + c];
#pragma unroll
            for (int bi = 0; bi < 8; bi++) {
                acc[bi] += w0 * ctx_s[bi][k] + w1 * ctx_s[bi][k + 1]
                         + w2 * ctx_s[bi][k + 2] + w3 * ctx_s[bi][k + 3];
            }
        }
#pragma unroll
        for (int bi = 0; bi < 8; bi++) qp[w][bi][lane] = acc[bi];
    }
    __syncthreads();

    {
        int bi = w;
        float s = 0.f;
#pragma unroll
        for (int ww = 0; ww < 8; ww++) s += qp[ww][bi][lane];
        q_s[bi][lane] = s;
    }
    __syncthreads();

    int d = t;
    const float4* wk = (const float4*)(Wk + (size_t)d * 256 + cx * 32);
#pragma unroll
    for (int hl = 0; hl < 2; hl++) {
        float4 w0 = wk[hl * 4], w1 = wk[hl * 4 + 1], w2 = wk[hl * 4 + 2], w3 = wk[hl * 4 + 3];
#pragma unroll
        for (int bi = 0; bi < 8; bi++) {
            const float4* qv = (const float4*)(&q_s[bi][hl * 16]);
            float s = dot4(w0, qv[0]) + dot4(w1, qv[1]) + dot4(w2, qv[2]) + dot4(w3, qv[3]);
            g_u[(size_t)(by * 8 + bi) * (HH * DD) + (cx * 2 + hl) * 256 + d] = s;
        }
    }
}

// ---------------- Kernel 3: attention per batch; w -> gmem -------------------
#define OFF_CE   0
#define OFF_ATT  (C1 * DD * 4)                  // 103424
#define OFF_VMI  (OFF_ATT + HH * AS * 4)        // +6656
#define SMEM_A_BYTES (OFF_VMI + 104 * 4 + 16)   // ~110.5KB -> occ 2

__global__ void __launch_bounds__(512, 2) k_attn(
    const float* __restrict__ clus, const void* __restrict__ vmask,
    const void* __restrict__ mask)
{
    extern __shared__ __align__(16) char smraw[];
    float* ce  = (float*)(smraw + OFF_CE);
    float* att = (float*)(smraw + OFF_ATT);
    int*   vmi = (int*)(smraw + OFF_VMI);

    int b = blockIdx.x, t = threadIdx.x;
    int lane = t & 31, warp = t >> 5;

    int mode = detect_mode(mask, t);

    {
        const float4* cg = (const float4*)(clus + (size_t)b * C1 * DD);
        float4* d4 = (float4*)ce;
        for (int i = t; i < C1 * DD / 4; i += 512) d4[i] = cg[i];
    }
    if (t < C1) vmi[t] = readb(vmask, b * C1 + t, mode) ? 1 : 0;
    __syncthreads();
    if (t == 0) {
        int all = 1;
        for (int j = 1; j < C1; j++) all &= vmi[j];
        vmi[0] = !all;
    }
    __syncthreads();

    const float4* ce4 = (const float4*)ce;
    int hg = warp & 3;       // head group: heads hg*4 .. hg*4+3
    int qq = warp >> 2;      // quarter index 0..3

    // ---- scores: warp = (hg, j-quarter); 2 passes of 2 heads ---------------
    {
        int jbeg = qq * 26;
        int jend = (qq == 3) ? C1 : jbeg + 26;
        const float4* up = (const float4*)(g_u + (size_t)b * (HH * DD));
#pragma unroll
        for (int pp = 0; pp < 2; pp++) {
            int ha = hg * 4 + pp * 2, hb = ha + 1;
            float4 ua0 = up[ha * 64 + lane * 2], ub0 = up[ha * 64 + lane * 2 + 1];
            float4 ua1 = up[hb * 64 + lane * 2], ub1 = up[hb * 64 + lane * 2 + 1];
            for (int j = jbeg; j < jend; j++) {
                float4 c0 = ce4[j * 64 + lane * 2], c1 = ce4[j * 64 + lane * 2 + 1];
                float p0 = dot4(ua0, c0) + dot4(ub0, c1);
                float p1 = dot4(ua1, c0) + dot4(ub1, c1);
#pragma unroll
                for (int o = 16; o; o >>= 1) {
                    p0 += __shfl_xor_sync(0xffffffffu, p0, o);
                    p1 += __shfl_xor_sync(0xffffffffu, p1, o);
                }
                if (lane == 0) {
                    int msk = vmi[j];
                    att[ha * AS + j] = msk ? NEGV : p0 * 0.25f;
                    att[hb * AS + j] = msk ? NEGV : p1 * 0.25f;
                }
            }
        }
    }
    __syncthreads();

    // ---- softmax: warp = head ----------------------------------------------
    {
        int h = warp;
        float v[4];
#pragma unroll
        for (int k = 0; k < 4; k++) {
            int j = lane + 32 * k;
            v[k] = (j < C1) ? att[h * AS + j] : -3.0e38f;
        }
        float m = fmaxf(fmaxf(v[0], v[1]), fmaxf(v[2], v[3]));
#pragma unroll
        for (int o = 16; o; o >>= 1) m = fmaxf(m, __shfl_xor_sync(0xffffffffu, m, o));
        float e[4], s = 0.f;
#pragma unroll
        for (int k = 0; k < 4; k++) {
            int j = lane + 32 * k;
            e[k] = (j < C1) ? expf(v[k] - m) : 0.f;
            s += e[k];
        }
#pragma unroll
        for (int o = 16; o; o >>= 1) s += __shfl_xor_sync(0xffffffffu, s, o);
        float inv = 1.0f / s;
#pragma unroll
        for (int k = 0; k < 4; k++) {
            int j = lane + 32 * k;
            if (j < C1) att[h * AS + j] = e[k] * inv;
        }
    }
    __syncthreads();

    // ---- wsum: warp = (hg, d-quarter); regs -> g_w directly ------------------
    {
        unsigned long long A0 = 0ull, A1 = 0ull, A2 = 0ull, A3 = 0ull;
        const unsigned long long* ce2 = (const unsigned long long*)ce;
        const float* a0 = att + (hg * 4 + 0) * AS;
        const float* a1 = att + (hg * 4 + 1) * AS;
        const float* a2 = att + (hg * 4 + 2) * AS;
        const float* a3 = att + (hg * 4 + 3) * AS;
        int idx = qq * 32 + lane;
        for (int j = 0; j < C1; j++) {
            unsigned long long c = ce2[j * 128 + idx];
            fma2(A0, pack2(a0[j]), c);
            fma2(A1, pack2(a1[j]), c);
            fma2(A2, pack2(a2[j]), c);
            fma2(A3, pack2(a3[j]), c);
        }
        int dbase = qq * 64 + lane * 2;
        float* gw = g_w + (size_t)b * (HH * DD);
        U64F2 u0, u1, u2, u3;
        u0.u = A0; u1.u = A1; u2.u = A2; u3.u = A3;
        *(float2*)(gw + (hg * 4 + 0) * 256 + dbase) = u0.f;
        *(float2*)(gw + (hg * 4 + 1) * 256 + dbase) = u1.f;
        *(float2*)(gw + (hg * 4 + 2) * 256 + dbase) = u2.f;
        *(float2*)(gw + (hg * 4 + 3) * 256 + dbase) = u3.f;
    }
}

// ---------------- Kernel 4: weight chain (2 batches/CTA) + logits + outputs --
#define G_W    0
#define G_SCR  (G_W + 2 * WROW * 4)             // 33280
#define G_GL   (G_SCR + 2 * 8 * 256 * 4)        // +16384
#define G_GO   (G_GL + 2048)
#define G_TV   (G_GO + 2048)
#define G_LG   (G_TV + 2048)
#define G_RED  (G_LG + 2 * AS * 4)
#define G_VMI  (G_RED + 16)
#define G_SEL  (G_VMI + 2 * 104 * 4)
#define SMEM_G_BYTES (G_SEL + 16)

__global__ void __launch_bounds__(512) k_glout(
    const float* __restrict__ depot, const float* __restrict__ clus,
    const float* __restrict__ cur,   const void*  __restrict__ vmask,
    const void*  __restrict__ mask,
    const float* __restrict__ Wv,    const float* __restrict__ Wks,
    const float* __restrict__ Wo,    float* __restrict__ out)
{
    extern __shared__ __align__(16) char smg[];
    float* w_sh = (float*)(smg + G_W);
    float* scr  = (float*)(smg + G_SCR);
    float* gl   = (float*)(smg + G_GL);
    float* go   = (float*)(smg + G_GO);
    float* tv   = (float*)(smg + G_TV);
    float* lg   = (float*)(smg + G_LG);
    float* red  = (float*)(smg + G_RED);
    int*   vmi  = (int*)(smg + G_VMI);
    int*   seli = (int*)(smg + G_SEL);

    int b0 = blockIdx.x * 2, t = threadIdx.x;
    int lane = t & 31, warp = t >> 5;

    int mode = detect_mode(mask, t);

    // load w for both batches; visited masks
    {
        const float4* gw4 = (const float4*)(g_w + (size_t)b0 * (HH * DD));
        for (int i = t; i < 2048; i += 512) {
            int bi = i >> 10, rem = i & 1023;
            int h = rem >> 6, d4 = rem & 63;
            ((float4*)(w_sh + bi * WROW + h * WS))[d4] = gw4[i];
        }
    }
    if (t < 256) {
        int bi = t >> 7, j = t & 127;
        if (j < C1) vmi[bi * 104 + j] = readb(vmask, (b0 + bi) * C1 + j, mode) ? 1 : 0;
    }
    __syncthreads();
    if (t < 2) {
        int all = 1;
        for (int j = 1; j < C1; j++) all &= vmi[t * 104 + j];
        vmi[t * 104] = !all;
    }
    __syncthreads();

    int c4 = t & 63, g = t >> 6;   // cols 4c4..4c4+3, d-group g (8x32)
    int h4 = c4 >> 2;

    // ---- gl: Wv loaded once, applied to both batches -------------------------
    {
        const float4* wv4 = (const float4*)Wv;
        const float* w0r = w_sh + 0 * WROW + h4 * WS;
        const float* w1r = w_sh + 1 * WROW + h4 * WS;
        float4 a0 = make_float4(0.f, 0.f, 0.f, 0.f), a1 = a0;
        int d0 = g * 32;
#pragma unroll 8
        for (int i = 0; i < 32; i++) {
            int d = d0 + i;
            float4 wv = wv4[(size_t)d * 64 + c4];
            float f0 = w0r[d], f1 = w1r[d];
            a0.x += wv.x * f0; a0.y += wv.y * f0; a0.z += wv.z * f0; a0.w += wv.w * f0;
            a1.x += wv.x * f1; a1.y += wv.y * f1; a1.z += wv.z * f1; a1.w += wv.w * f1;
        }
        ((float4*)scr)[(0 * 8 + g) * 64 + c4] = a0;
        ((float4*)scr)[(1 * 8 + g) * 64 + c4] = a1;
    }
    __syncthreads();
    {
        int bi = t >> 8, c = t & 255;
        float s = 0.f;
#pragma unroll
        for (int gg = 0; gg < 8; gg++) s += scr[(bi * 8 + gg) * 256 + c];
        gl[bi * 256 + c] = s;
    }
    __syncthreads();

    // ---- go = gl @ Wo ---------------------------------------------------------
    {
        const float4* wo4 = (const float4*)Wo;
        float4 a0 = make_float4(0.f, 0.f, 0.f, 0.f), a1 = a0;
        int d0 = g * 32;
#pragma unroll 8
        for (int i = 0; i < 32; i++) {
            int d = d0 + i;
            float4 wv = wo4[(size_t)d * 64 + c4];
            float f0 = gl[d], f1 = gl[256 + d];
            a0.x += wv.x * f0; a0.y += wv.y * f0; a0.z += wv.z * f0; a0.w += wv.w * f0;
            a1.x += wv.x * f1; a1.y += wv.y * f1; a1.z += wv.z * f1; a1.w += wv.w * f1;
        }
        ((float4*)scr)[(0 * 8 + g) * 64 + c4] = a0;
        ((float4*)scr)[(1 * 8 + g) * 64 + c4] = a1;
    }
    __syncthreads();
    {
        int bi = t >> 8, c = t & 255;
        float s = 0.f;
#pragma unroll
        for (int gg = 0; gg < 8; gg++) s += scr[(bi * 8 + gg) * 256 + c];
        go[bi * 256 + c] = s;
    }
    __syncthreads();

    // ---- tv: warp per row, Wks row loaded once, both batches -----------------
    {
        const float4* wk4 = (const float4*)Wks;
        const float4* go4 = (const float4*)go;
        float4 gA0 = go4[lane], gB0 = go4[32 + lane];
        float4 gA1 = go4[64 + lane], gB1 = go4[96 + lane];
        for (int r = warp; r < DD; r += 16) {
            float4 wA = wk4[(size_t)r * 64 + lane];
            float4 wB = wk4[(size_t)r * 64 + 32 + lane];
            float s0 = dot4(wA, gA0) + dot4(wB, gB0);
            float s1 = dot4(wA, gA1) + dot4(wB, gB1);
#pragma unroll
            for (int o = 16; o; o >>= 1) {
                s0 += __shfl_xor_sync(0xffffffffu, s0, o);
                s1 += __shfl_xor_sync(0xffffffffu, s1, o);
            }
            if (lane == 0) { tv[r] = s0; tv[256 + r] = s1; }
        }
    }
    __syncthreads();

    // ---- logits: warp = (bi, j-offset); ce via L2 ------------------------------
    {
        int bi = warp & 1, jw = warp >> 1;
        const float4* cg = (const float4*)(clus + (size_t)(b0 + bi) * C1 * DD);
        const float4* tv4 = (const float4*)tv;
        float4 t0 = tv4[bi * 64 + lane * 2], t1 = tv4[bi * 64 + lane * 2 + 1];
        for (int j = jw; j < C1; j += 8) {
            float4 c0 = cg[j * 64 + lane * 2], c1 = cg[j * 64 + lane * 2 + 1];
            float s = dot4(t0, c0) + dot4(t1, c1);
#pragma unroll
            for (int o = 16; o; o >>= 1) s += __shfl_xor_sync(0xffffffffu, s, o);
            if (lane == 0) {
                float l = tanhf(s * (1.0f / 16.0f)) * 10.0f;
                lg[bi * AS + j] = vmi[bi * 104 + j] ? NEGV : l;
            }
        }
    }
    __syncthreads();

    // ---- log_softmax + argmax: warp 0 -> batch 0, warp 1 -> batch 1 ------------
    if (warp < 2) {
        int bi = warp;
        float m = -3.0e38f; int mi = 0x7fffffff;
        for (int j = lane; j < C1; j += 32) {
            float v = lg[bi * AS + j];
            if (v > m) { m = v; mi = j; }
        }
#pragma unroll
        for (int o = 16; o; o >>= 1) {
            float om = __shfl_xor_sync(0xffffffffu, m, o);
            int   oi = __shfl_xor_sync(0xffffffffu, mi, o);
            if (om > m || (om == m && oi < mi)) { m = om; mi = oi; }
        }
        float s = 0.f;
        for (int j = lane; j < C1; j += 32) s += expf(lg[bi * AS + j] - m);
#pragma unroll
        for (int o = 16; o; o >>= 1) s += __shfl_xor_sync(0xffffffffu, s, o);
        if (lane == 0) { red[bi] = m + logf(s); seli[bi] = mi; }
    }
    __syncthreads();

    // ---- outputs: 256 threads per batch -----------------------------------------
    {
        int bi = t >> 8, d = t & 255;
        int b = b0 + bi;
        int sel = seli[bi];
        float lse = red[bi];
        float se = clus[(size_t)b * C1 * DD + (size_t)sel * 256 + d];
        int cb = (BB + b) * 4;
        float s = g_part[(size_t)(cb + 0) * 256 + d] + g_part[(size_t)(cb + 1) * 256 + d]
                + g_part[(size_t)(cb + 2) * 256 + d] + g_part[(size_t)(cb + 3) * 256 + d];
        float den = fmaxf((float)(g_cnt[cb] + g_cnt[cb + 1] + g_cnt[cb + 2] + g_cnt[cb + 3]), 1.0f);
        size_t oa = (size_t)b * 1024;
        out[oa + d]       = s / den;
        out[oa + 256 + d] = cur[(size_t)b * DD + d];
        out[oa + 512 + d] = se;
        out[oa + 768 + d] = depot[(size_t)b * DD + d];
        out[262144 + (size_t)b * 256 + d] = se;
        if (d == 0) out[327680 + b] = (float)sel;
        if (d < C1) out[327936 + (size_t)b * C1 + d] = lg[bi * AS + d] - lse;
    }
}

extern "C" void kernel_launch(void* const* d_in, const int* in_sizes, int n_in,
                              void* d_out, int out_size) {
    const float* depot = (const float*)d_in[0];
    const float* clus  = (const float*)d_in[1];
    const float* cur   = (const float*)d_in[2];
    const float* node  = (const float*)d_in[3];
    const void*  mask  = d_in[4];
    const void*  cmask = d_in[5];
    const void*  vmask = d_in[6];
    const float* Wq    = (const float*)d_in[7];
    const float* Wk    = (const float*)d_in[8];
    const float* Wv    = (const float*)d_in[9];
    const float* Wks   = (const float*)d_in[10];
    const float* Wo    = (const float*)d_in[11];
    float* out = (float*)d_out;

    cudaFuncSetAttribute(k_attn,  cudaFuncAttributeMaxDynamicSharedMemorySize, SMEM_A_BYTES);
    cudaFuncSetAttribute(k_glout, cudaFuncAttributeMaxDynamicSharedMemorySize, SMEM_G_BYTES);

    k_nodes_part<<<dim3(4, BB), 256>>>(node, mask, cmask);
    k_qu<<<dim3(8, 32), 256>>>(cur, depot, Wq, Wk);
    k_attn<<<BB, 512, SMEM_A_BYTES>>>(clus, vmask, mask);
    k_glout<<<BB / 2, 512, SMEM_G_BYTES>>>(depot, clus, cur, vmask, mask, Wv, Wks, Wo, out);
}